// round 17
// baseline (speedup 1.0000x reference)
#include <cuda_runtime.h>
#include <cuda_fp16.h>
#include <math.h>
#include <stdint.h>

#define Bz 16
#define C 256
#define H 48
#define W 160
#define HW (H*W)            // 7680
#define CHW (C*HW)          // 1966080

typedef unsigned long long ull;

// Scratch (__device__ globals; no allocations allowed)
__device__ float  g_G[(size_t)Bz * 4 * 9 * HW];
__device__ int    g_y0[Bz * HW];
__device__ float  g_wy[Bz * HW];
__device__ float  g_samp0[Bz * HW];
__device__ __half g_Ah[C * C];   // w_ext[:,1:] f16, blocked [k/8][m][8k]

// ===================== PTX helpers ==============================
__device__ __forceinline__ void fma2(ull& d, ull a, ull b) {
    asm("fma.rn.f32x2 %0, %1, %2, %0;" : "+l"(d) : "l"(a), "l"(b));
}
__device__ __forceinline__ ull pack2(float lo, float hi) {
    ull r; asm("mov.b64 %0, {%1, %2};" : "=l"(r) : "f"(lo), "f"(hi)); return r;
}
__device__ __forceinline__ uint32_t smem_u32(const void* p) {
    uint32_t a;
    asm("{ .reg .u64 t; cvta.to.shared.u64 t, %1; cvt.u32.u64 %0, t; }" : "=r"(a) : "l"(p));
    return a;
}
#define CP_ASYNC_16(dst, src) \
    asm volatile("cp.async.cg.shared.global [%0], [%1], 16;" :: "r"(dst), "l"(src))
#define CP_COMMIT() asm volatile("cp.async.commit_group;" ::: "memory")
#define CP_WAIT(n)  asm volatile("cp.async.wait_group %0;" :: "n"(n) : "memory")

__device__ __forceinline__ void ldsm_x4(uint32_t addr, uint32_t* r) {
    asm volatile("ldmatrix.sync.aligned.m8n8.x4.shared.b16 {%0,%1,%2,%3}, [%4];"
        : "=r"(r[0]), "=r"(r[1]), "=r"(r[2]), "=r"(r[3]) : "r"(addr));
}
__device__ __forceinline__ void ldsm_x2_trans(uint32_t addr, uint32_t* r) {
    asm volatile("ldmatrix.sync.aligned.m8n8.x2.trans.shared.b16 {%0,%1}, [%2];"
        : "=r"(r[0]), "=r"(r[1]) : "r"(addr));
}

// m16n8k16 f16 MMA, f32 accumulate
__device__ __forceinline__ void mma_f16(float* d,
                                        uint32_t a0, uint32_t a1, uint32_t a2, uint32_t a3,
                                        uint32_t b0, uint32_t b1) {
    asm volatile(
        "mma.sync.aligned.m16n8k16.row.col.f32.f16.f16.f32 "
        "{%0,%1,%2,%3}, {%4,%5,%6,%7}, {%8,%9}, {%0,%1,%2,%3};"
        : "+f"(d[0]), "+f"(d[1]), "+f"(d[2]), "+f"(d[3])
        : "r"(a0), "r"(a1), "r"(a2), "r"(a3), "r"(b0), "r"(b1));
}

// ---------------------------------------------------------------------------
// Kernel 0: w_ext[:,1:] -> g_Ah blocked [k/8][m][8k], f16.
// ---------------------------------------------------------------------------
__global__ void prepA_kernel(const float* __restrict__ w_ext)
{
    const int m = blockIdx.x, k = threadIdx.x;
    g_Ah[(k >> 3) * (C * 8) + m * 8 + (k & 7)] =
        __float2half(__ldg(&w_ext[(size_t)m * 257 + 1 + k]));
}

// ---------------------------------------------------------------------------
// Kernel 1: conv phase A, 4 channel-chunks (960 blocks).
// ---------------------------------------------------------------------------
#define CCH 64
__global__ __launch_bounds__(256) void convA_kernel(const float* __restrict__ f,
                                                    const float* __restrict__ w_disp)
{
    __shared__ ull sW2[CCH * 9];
    const int tid   = threadIdx.x;
    const int chunk = blockIdx.y;
    const int b     = blockIdx.z;
    const int p2    = blockIdx.x * 512 + tid * 2;

    for (int i = tid; i < CCH * 9; i += 256) {
        float w = __ldg(&w_disp[chunk * CCH * 9 + i]);
        sW2[i] = pack2(w, w);
    }
    __syncthreads();

    const float* Fb = f + (size_t)b * CHW + (size_t)chunk * CCH * HW;
    ull acc[9];
    #pragma unroll
    for (int j = 0; j < 9; j++) acc[j] = 0ull;

    #pragma unroll 4
    for (int c = 0; c < CCH; c++) {
        ull v = *(const ull*)&Fb[(size_t)c * HW + p2];
        #pragma unroll
        for (int j = 0; j < 9; j++) fma2(acc[j], sW2[c * 9 + j], v);
    }
    #pragma unroll
    for (int j = 0; j < 9; j++)
        *(ull*)&g_G[((size_t)((b * 4 + chunk) * 9 + j)) * HW + p2] = acc[j];
}

// ---------------------------------------------------------------------------
// Kernel 2: 3x3 combine, tanh -> disp, sampling params.
// ---------------------------------------------------------------------------
__global__ __launch_bounds__(256) void phaseB_kernel(const float* __restrict__ P2,
                                                     const float* __restrict__ b_disp)
{
    const int b = blockIdx.y;
    const int p = blockIdx.x * 256 + threadIdx.x;
    const int y = p / W, x = p % W;

    float s = 0.f;
    #pragma unroll
    for (int dy = -1; dy <= 1; dy++) {
        int yy = y + dy;
        if (yy < 0 || yy >= H) continue;
        #pragma unroll
        for (int dx = -1; dx <= 1; dx++) {
            int xx = x + dx;
            if (xx < 0 || xx >= W) continue;
            int j = (dy + 1) * 3 + (dx + 1);
            #pragma unroll
            for (int ch = 0; ch < 4; ch++)
                s += g_G[((size_t)((b * 4 + ch) * 9 + j)) * HW + yy * W + xx];
        }
    }
    const float dval = 0.1f * tanhf(s + __ldg(&b_disp[0]));

    const float fyv = __ldg(&P2[b * 12 + 5]) * 0.0625f;
    const float cyv = __ldg(&P2[b * 12 + 6]) * 0.0625f;
    const float Tyv = __ldg(&P2[b * 12 + 7]) * 0.0625f;
    const float denom = fabsf(fyv * 1.65f + Tyv) + 1e-10f;

    const float yf    = (float)y;
    const float ysb   = fmaxf(1.535f * (yf - cyv) / (2.f * (1.65f - 0.5f * 1.535f)), 0.f) * (1.f / 24.f);
    const float ybase = -1.f + yf * (2.f / 47.f);
    const float gy    = ybase + ysb + dval;

    float iy  = fminf(fmaxf((gy + 1.f) * 0.5f * 47.f, 0.f), 47.f);
    float y0f = floorf(iy);
    float wy  = iy - y0f;
    int y0 = (int)y0f;
    int y1 = min(y0 + 1, H - 1);

    const float sc = fyv * 0.54f / denom;
    float d0 = fmaxf(sc * (y0f - cyv), 0.f);
    float d1 = fmaxf(sc * ((float)y1 - cyv), 0.f);

    const int gi = b * HW + p;
    g_y0[gi]    = y0;
    g_wy[gi]    = wy;
    g_samp0[gi] = d0 + wy * (d1 - d0);
}

// ---------------------------------------------------------------------------
// Kernel 3: f16 m16n8k16 mma.sync GEMM, 2 CTAs/SM, ROWS-WINDOW gather.
// 256 threads (8 warps 4m x 2n), GM=256, GN=64, K chunks of 16.
// Per chunk: coalesced float4 cp.async of a R_MAX=10-row feature window;
// stage selects per-pixel rows (conflict-free LDS) + lerp -> f16 Bh.
// Tile y0 span mathematically <= 7 (gy spread <= 0.279), so 10 rows cover
// y0..y1 always.
// ---------------------------------------------------------------------------
#define GM 256
#define GN 64
#define GK 16
#define NCH (C / GK)                    // 16
#define RMAX 10
#define BHSTR 144                       // f16 Bh row pitch (bytes)
#define ABUF  (GM * GK * 2)             // 8192 B per slot (f16 blocked)
#define RBUF  (GK * RMAX * GN * 4)      // 40960 B per slot
#define OFF_A    0                      // 3 slots: 24576
#define OFF_ROWS 24576                  // 2 slots: 81920 -> 106496
#define OFF_BH   106496                 // 2304 -> 108800
#define OFF_CTL  108800
#define SMEM_TOT (OFF_CTL + 1152)       // 109952

__global__ __launch_bounds__(256, 2) void gemm_mma_kernel(
    const float* __restrict__ f,
    const float* __restrict__ w_ext,
    const float* __restrict__ b_ext,
    const float* __restrict__ alpha,
    float* __restrict__ out)
{
    extern __shared__ __align__(16) char smem[];
    const uint32_t sb = smem_u32(smem);

    int*   sRy0 = (int*)  (smem + OFF_CTL);          // 64 ints
    int*   sRy1 = (int*)  (smem + OFF_CTL + 256);
    float* sWyv = (float*)(smem + OFF_CTL + 512);
    float* sSm  = (float*)(smem + OFF_CTL + 768);
    int*   sMM  = (int*)  (smem + OFF_CTL + 1024);

    const int tid  = threadIdx.x;
    const int warp = tid >> 5;
    const int lane = tid & 31;
    const int lg   = lane >> 2;
    const int lt   = lane & 3;
    const int wm   = (warp >> 1) * 64;     // 0,64,128,192
    const int wn   = (warp & 1) * 32;      // 0,32

    const int b  = blockIdx.z;
    const int n0 = blockIdx.x * GN;
    const float* Fb = f + (size_t)b * CHW;

    if (tid == 0) sMM[0] = 1 << 30;
    __syncthreads();

    int y0v = 0, y1v = 0;
    if (tid < GN) {
        int p = n0 + tid;
        y0v = g_y0[b * HW + p];
        y1v = min(y0v + 1, H - 1);
        sWyv[tid] = g_wy[b * HW + p];
        sSm[tid]  = g_samp0[b * HW + p];
        atomicMin(&sMM[0], y0v);
    }
    __syncthreads();
    const int miny = sMM[0];
    const int x0m  = n0 % W;
    if (tid < GN) {
        sRy0[tid] = y0v - miny;
        sRy1[tid] = y1v - miny;
    }
    // visibility of sRy0/sRy1 guaranteed by the first mainloop __syncthreads

    // ---- async prefetch: A -> slot c%3, rows window -> slot c&1 ----
    auto prefetch = [&](int c) {
        const uint32_t ab = sb + OFF_A    + (c % 3) * ABUF;
        const uint32_t rb = sb + OFF_ROWS + (c & 1) * RBUF;
        #pragma unroll
        for (int i = 0; i < 2; i++) {
            int e = tid + i * 256;            // 512 16B units of A
            const __half* src = g_Ah + (size_t)(c * 2 + (e >> 8)) * (C * 8) + (e & 255) * 8;
            CP_ASYNC_16(ab + e * 16, src);
        }
        #pragma unroll
        for (int i = 0; i < 10; i++) {
            int e   = tid + i * 256;          // 2560 float4 units: [k][r][q]
            int k   = e / 160;
            int rem = e - k * 160;
            int r   = rem >> 4;
            int q   = rem & 15;
            int row = miny + r; if (row > H - 1) row = H - 1;
            int x   = x0m + q * 4; if (x >= W) x -= W;
            const float* src = Fb + (size_t)(c * GK + k) * HW + row * W + x;
            CP_ASYNC_16(rb + (uint32_t)e * 16, src);
        }
        CP_COMMIT();
    };

    float acc[4][4][4];
    #pragma unroll
    for (int mi = 0; mi < 4; mi++)
        #pragma unroll
        for (int nj = 0; nj < 4; nj++)
            #pragma unroll
            for (int t = 0; t < 4; t++) acc[mi][nj][t] = 0.f;

    const uint32_t laneoff = (uint32_t)(((lane >> 4) * GM + (lane & 15)) * 16);
    const uint32_t bh = sb + OFF_BH;

    prefetch(0);
    prefetch(1);

    for (int c = 0; c < NCH; c++) {
        if (c < NCH - 1) CP_WAIT(1); else CP_WAIT(0);
        __syncthreads();

        // ---- stage: select rows + lerp -> f16 Bh[k][n] ----
        {
            const float* Rw = (const float*)(smem + OFF_ROWS + (c & 1) * RBUF);
            #pragma unroll
            for (int i = 0; i < 4; i++) {
                int e = tid + i * 256;        // 1024 = 16k x 64n
                int k = e >> 6;
                int n = e & 63;
                float v0 = Rw[(k * RMAX + sRy0[n]) * GN + n];
                float v1 = Rw[(k * RMAX + sRy1[n]) * GN + n];
                float r  = fmaf(sWyv[n], v1 - v0, v0);
                *(__half*)(smem + OFF_BH + k * BHSTR + n * 2) = __float2half(r);
            }
        }
        __syncthreads();

        // ---- compute: one K16 step ----
        const uint32_t abase = sb + OFF_A + (c % 3) * ABUF;
        uint32_t af[4][4];
        #pragma unroll
        for (int mi = 0; mi < 4; mi++)
            ldsm_x4(abase + (uint32_t)((wm + mi * 16) * 16) + laneoff, af[mi]);
        uint32_t bf[4][2];
        #pragma unroll
        for (int nj = 0; nj < 4; nj++)
            ldsm_x2_trans(bh + (uint32_t)((lane & 15) * BHSTR + (wn + nj * 8) * 2), bf[nj]);
        #pragma unroll
        for (int mi = 0; mi < 4; mi++)
            #pragma unroll
            for (int nj = 0; nj < 4; nj++)
                mma_f16(acc[mi][nj],
                        af[mi][0], af[mi][1], af[mi][2], af[mi][3],
                        bf[nj][0], bf[nj][1]);

        if (c + 2 < NCH) prefetch(c + 2);
    }

    // ---- fused epilogue ----
    const float al = __ldg(&alpha[0]);
    #pragma unroll
    for (int mi = 0; mi < 4; mi++) {
        const int r0 = wm + mi * 16 + lg;
        const float w0a = __ldg(&w_ext[(size_t)r0 * 257]);
        const float bea = __ldg(&b_ext[r0]);
        const float w0b = __ldg(&w_ext[(size_t)(r0 + 8) * 257]);
        const float beb = __ldg(&b_ext[r0 + 8]);
        #pragma unroll
        for (int nj = 0; nj < 4; nj++) {
            const int cl  = wn + nj * 8 + 2 * lt;
            const int col = n0 + cl;
            const float s0 = sSm[cl], s1 = sSm[cl + 1];

            size_t oa = ((size_t)b * C + r0) * HW + col;
            size_t ob = oa + (size_t)8 * HW;

            float2 fa = *(const float2*)(f + oa);
            float2 fb = *(const float2*)(f + ob);
            float2 ra, rb;
            ra.x = fmaxf(fa.x + al * (acc[mi][nj][0] + w0a * s0 + bea), 0.f);
            ra.y = fmaxf(fa.y + al * (acc[mi][nj][1] + w0a * s1 + bea), 0.f);
            rb.x = fmaxf(fb.x + al * (acc[mi][nj][2] + w0b * s0 + beb), 0.f);
            rb.y = fmaxf(fb.y + al * (acc[mi][nj][3] + w0b * s1 + beb), 0.f);
            *(float2*)(out + oa) = ra;
            *(float2*)(out + ob) = rb;
        }
    }
}

// ---------------------------------------------------------------------------
extern "C" void kernel_launch(void* const* d_in, const int* in_sizes, int n_in,
                              void* d_out, int out_size)
{
    const float* features = (const float*)d_in[0];
    const float* P2       = (const float*)d_in[1];
    const float* w_disp   = (const float*)d_in[2];
    const float* b_disp   = (const float*)d_in[3];
    const float* w_ext    = (const float*)d_in[4];
    const float* b_ext    = (const float*)d_in[5];
    const float* alpha    = (const float*)d_in[6];
    float* out = (float*)d_out;

    cudaFuncSetAttribute(gemm_mma_kernel,
                         cudaFuncAttributeMaxDynamicSharedMemorySize, SMEM_TOT);

    prepA_kernel <<<C, C>>>(w_ext);
    convA_kernel <<<dim3(HW / 512, 4, Bz), 256>>>(features, w_disp);
    phaseB_kernel<<<dim3(HW / 256, Bz), 256>>>(P2, b_disp);
    gemm_mma_kernel<<<dim3(HW / GN, 1, Bz), 256, SMEM_TOT>>>(
        features, w_ext, b_ext, alpha, out);
}